// round 1
// baseline (speedup 1.0000x reference)
#include <cuda_runtime.h>

// LocalityEntropyLoss: feat_map [T=256, F=401408] f32
// L1 = mean over rows of entropy(softmax(row))
// L2 = -entropy(softmax(mean over rows))
// Using m=0 (inputs are N(0,1), e^x bounded ~100): entropy = ln S - U/S,
// S = sum e^x, U = sum x e^x.

#define T_ROWS 256
#define F_COLS 401408
#define THREADS 256
#define VEC 4
#define CPB (THREADS * VEC)          // 1024 columns per block
#define NBLK (F_COLS / CPB)          // 392 blocks
#define NWARP (THREADS / 32)         // 8

__device__ float g_colsum[F_COLS];
__device__ float g_rowS[T_ROWS];
__device__ float g_rowU[T_ROWS];
__device__ float g_aS;
__device__ float g_aU;

__global__ void init_kernel() {
    int t = threadIdx.x;
    if (t < T_ROWS) { g_rowS[t] = 0.0f; g_rowU[t] = 0.0f; }
    if (t == 0) { g_aS = 0.0f; g_aU = 0.0f; }
}

// Main fused pass: per-row (S,U) partials + full column sums.
// Each block owns CPB contiguous columns across ALL rows.
__global__ __launch_bounds__(THREADS) void main_pass(const float* __restrict__ x) {
    __shared__ float shS[NWARP][T_ROWS];
    __shared__ float shU[NWARP][T_ROWS];

    const int tid  = threadIdx.x;
    const int wid  = tid >> 5;
    const int lane = tid & 31;
    const long long colBase = (long long)blockIdx.x * CPB + tid * VEC;
    const float4* p = (const float4*)(x + colBase);
    const int stride4 = F_COLS / 4;

    float c0 = 0.f, c1 = 0.f, c2 = 0.f, c3 = 0.f;

#define PROC_ROW(v, rr)                                                        \
    do {                                                                       \
        c0 += (v).x; c1 += (v).y; c2 += (v).z; c3 += (v).w;                    \
        float e0 = __expf((v).x), e1 = __expf((v).y);                          \
        float e2 = __expf((v).z), e3 = __expf((v).w);                          \
        float s = (e0 + e1) + (e2 + e3);                                       \
        float u = fmaf((v).x, e0, fmaf((v).y, e1, fmaf((v).z, e2, (v).w * e3)));\
        _Pragma("unroll")                                                      \
        for (int o = 16; o > 0; o >>= 1) {                                     \
            s += __shfl_xor_sync(0xffffffffu, s, o);                           \
            u += __shfl_xor_sync(0xffffffffu, u, o);                           \
        }                                                                      \
        if (lane == 0) { shS[wid][rr] = s; shU[wid][rr] = u; }                 \
    } while (0)

    for (int r = 0; r < T_ROWS; r += 4) {
        // 4 independent loads in flight (MLP)
        float4 va = __ldcs(&p[(long long)(r + 0) * stride4]);
        float4 vb = __ldcs(&p[(long long)(r + 1) * stride4]);
        float4 vc = __ldcs(&p[(long long)(r + 2) * stride4]);
        float4 vd = __ldcs(&p[(long long)(r + 3) * stride4]);
        PROC_ROW(va, r + 0);
        PROC_ROW(vb, r + 1);
        PROC_ROW(vc, r + 2);
        PROC_ROW(vd, r + 3);
    }
#undef PROC_ROW

    // Column sums are complete for this block's columns: plain store.
    float4 cs = make_float4(c0, c1, c2, c3);
    *(float4*)(g_colsum + colBase) = cs;

    __syncthreads();

    // Thread t combines the 8 warp partials for row t, one global atomic each.
    float s = 0.f, u = 0.f;
#pragma unroll
    for (int w = 0; w < NWARP; w++) { s += shS[w][tid]; u += shU[w][tid]; }
    atomicAdd(&g_rowS[tid], s);
    atomicAdd(&g_rowU[tid], u);
}

// Entropy stats of the batch-mean vector (1.6 MB pass).
__global__ __launch_bounds__(256) void avg_pass() {
    __shared__ float shS[8];
    __shared__ float shU[8];
    const int tid  = threadIdx.x;
    const int wid  = tid >> 5;
    const int lane = tid & 31;
    const float inv = 1.0f / 256.0f;
    const int n4 = F_COLS / 4;

    float s = 0.f, u = 0.f;
    const float4* p = (const float4*)g_colsum;
    for (int i = blockIdx.x * blockDim.x + tid; i < n4; i += gridDim.x * blockDim.x) {
        float4 v = p[i];
        float a0 = v.x * inv, a1 = v.y * inv, a2 = v.z * inv, a3 = v.w * inv;
        float e0 = __expf(a0), e1 = __expf(a1), e2 = __expf(a2), e3 = __expf(a3);
        s += (e0 + e1) + (e2 + e3);
        u = fmaf(a0, e0, u); u = fmaf(a1, e1, u);
        u = fmaf(a2, e2, u); u = fmaf(a3, e3, u);
    }
#pragma unroll
    for (int o = 16; o > 0; o >>= 1) {
        s += __shfl_xor_sync(0xffffffffu, s, o);
        u += __shfl_xor_sync(0xffffffffu, u, o);
    }
    if (lane == 0) { shS[wid] = s; shU[wid] = u; }
    __syncthreads();
    if (wid == 0) {
        s = (lane < 8) ? shS[lane] : 0.f;
        u = (lane < 8) ? shU[lane] : 0.f;
#pragma unroll
        for (int o = 4; o > 0; o >>= 1) {
            s += __shfl_xor_sync(0xffffffffu, s, o);
            u += __shfl_xor_sync(0xffffffffu, u, o);
        }
        if (lane == 0) { atomicAdd(&g_aS, s); atomicAdd(&g_aU, u); }
    }
}

__global__ void finalize_kernel(float* __restrict__ out) {
    __shared__ float sh[8];
    const int tid  = threadIdx.x;
    const int wid  = tid >> 5;
    const int lane = tid & 31;

    float S = g_rowS[tid];
    float U = g_rowU[tid];
    float ent = logf(S) - U / S;   // per-row entropy
#pragma unroll
    for (int o = 16; o > 0; o >>= 1)
        ent += __shfl_xor_sync(0xffffffffu, ent, o);
    if (lane == 0) sh[wid] = ent;
    __syncthreads();
    if (tid == 0) {
        float tot = 0.f;
#pragma unroll
        for (int w = 0; w < 8; w++) tot += sh[w];
        out[0] = tot * (1.0f / 256.0f);           // L1
        float Sa = g_aS, Ua = g_aU;
        out[1] = Ua / Sa - logf(Sa);              // L2 = -entropy(avg)
    }
}

extern "C" void kernel_launch(void* const* d_in, const int* in_sizes, int n_in,
                              void* d_out, int out_size) {
    const float* x = (const float*)d_in[0];
    float* out = (float*)d_out;
    init_kernel<<<1, 256>>>();
    main_pass<<<NBLK, THREADS>>>(x);
    avg_pass<<<256, 256>>>();
    finalize_kernel<<<1, 256>>>(out);
}

// round 3
// speedup vs baseline: 1.0547x; 1.0547x over previous
#include <cuda_runtime.h>

// LocalityEntropyLoss: feat_map [T=256, F=401408] f32
// L1 = mean over rows of entropy(softmax(row))
// L2 = -entropy(softmax(mean over rows))
// Inputs ~N(0,1): no max-subtraction needed (e^x <= ~100, S ~ 6.6e5, fp32-safe).
// entropy(row) = ln S - U/S,  S = sum e^x, U = sum x e^x.

#define T_ROWS 256
#define F_COLS 401408
#define THREADS 128
#define VEC 4
#define CPB (THREADS * VEC)          // 512 columns per block
#define NBLK (F_COLS / CPB)          // 784 blocks
#define NWARP (THREADS / 32)         // 4
#define UNROLL 8

__device__ float g_colsum[F_COLS];
__device__ float g_rowS[T_ROWS];
__device__ float g_rowU[T_ROWS];
__device__ float g_aS;
__device__ float g_aU;

__global__ void init_kernel() {
    int t = threadIdx.x;
    if (t < T_ROWS) { g_rowS[t] = 0.0f; g_rowU[t] = 0.0f; }
    if (t == 0) { g_aS = 0.0f; g_aU = 0.0f; }
}

// Main fused pass: per-row (S,U) partials + full column sums.
// Each block owns CPB contiguous columns across ALL rows.
__global__ __launch_bounds__(THREADS) void main_pass(const float* __restrict__ x) {
    // 3-step butterfly leaves lanes 0..3 holding disjoint partials of the warp:
    // store 4 partials per (warp, row); fold them once at the end of the block.
    __shared__ float shS[NWARP][T_ROWS][4];   // 16 KB
    __shared__ float shU[NWARP][T_ROWS][4];   // 16 KB

    const int tid  = threadIdx.x;
    const int wid  = tid >> 5;
    const int lane = tid & 31;
    const int colBase = blockIdx.x * CPB + tid * VEC;
    const float4* p = (const float4*)(x + colBase);
    const int stride4 = F_COLS / 4;

    float c0 = 0.f, c1 = 0.f, c2 = 0.f, c3 = 0.f;

#define PROC_ROW(v, rr)                                                         \
    do {                                                                        \
        c0 += (v).x; c1 += (v).y; c2 += (v).z; c3 += (v).w;                     \
        float e0 = __expf((v).x), e1 = __expf((v).y);                           \
        float e2 = __expf((v).z), e3 = __expf((v).w);                           \
        float s = (e0 + e1) + (e2 + e3);                                        \
        float u = fmaf((v).x, e0, fmaf((v).y, e1, fmaf((v).z, e2, (v).w * e3)));\
        s += __shfl_xor_sync(0xffffffffu, s, 16);                               \
        u += __shfl_xor_sync(0xffffffffu, u, 16);                               \
        s += __shfl_xor_sync(0xffffffffu, s, 8);                                \
        u += __shfl_xor_sync(0xffffffffu, u, 8);                                \
        s += __shfl_xor_sync(0xffffffffu, s, 4);                                \
        u += __shfl_xor_sync(0xffffffffu, u, 4);                                \
        if (lane < 4) { shS[wid][rr][lane] = s; shU[wid][rr][lane] = u; }       \
    } while (0)

    for (int r = 0; r < T_ROWS; r += UNROLL) {
        float4 v[UNROLL];
#pragma unroll
        for (int k = 0; k < UNROLL; k++)
            v[k] = __ldcs(&p[(r + k) * stride4]);   // 8 independent loads in flight
#pragma unroll
        for (int k = 0; k < UNROLL; k++)
            PROC_ROW(v[k], r + k);
    }
#undef PROC_ROW

    // Column sums are complete for this block's columns: plain store, no atomics.
    *(float4*)(g_colsum + colBase) = make_float4(c0, c1, c2, c3);

    __syncthreads();

    // Fold the 4x4 warp partials per row; 2 global atomics per row per block.
    for (int rr = tid; rr < T_ROWS; rr += THREADS) {
        float s = 0.f, u = 0.f;
#pragma unroll
        for (int w = 0; w < NWARP; w++) {
            float4 a = *(const float4*)shS[w][rr];
            float4 b = *(const float4*)shU[w][rr];
            s += (a.x + a.y) + (a.z + a.w);
            u += (b.x + b.y) + (b.z + b.w);
        }
        atomicAdd(&g_rowS[rr], s);
        atomicAdd(&g_rowU[rr], u);
    }
}

// Entropy stats of the batch-mean vector (1.6 MB pass).
__global__ __launch_bounds__(256) void avg_pass() {
    __shared__ float shS[8];
    __shared__ float shU[8];
    const int tid  = threadIdx.x;
    const int wid  = tid >> 5;
    const int lane = tid & 31;
    const float inv = 1.0f / 256.0f;
    const int n4 = F_COLS / 4;

    float s = 0.f, u = 0.f;
    const float4* p = (const float4*)g_colsum;
    for (int i = blockIdx.x * blockDim.x + tid; i < n4; i += gridDim.x * blockDim.x) {
        float4 v = p[i];
        float a0 = v.x * inv, a1 = v.y * inv, a2 = v.z * inv, a3 = v.w * inv;
        float e0 = __expf(a0), e1 = __expf(a1), e2 = __expf(a2), e3 = __expf(a3);
        s += (e0 + e1) + (e2 + e3);
        u = fmaf(a0, e0, u); u = fmaf(a1, e1, u);
        u = fmaf(a2, e2, u); u = fmaf(a3, e3, u);
    }
#pragma unroll
    for (int o = 16; o > 0; o >>= 1) {
        s += __shfl_xor_sync(0xffffffffu, s, o);
        u += __shfl_xor_sync(0xffffffffu, u, o);
    }
    if (lane == 0) { shS[wid] = s; shU[wid] = u; }
    __syncthreads();
    if (wid == 0) {
        s = (lane < 8) ? shS[lane] : 0.f;
        u = (lane < 8) ? shU[lane] : 0.f;
#pragma unroll
        for (int o = 4; o > 0; o >>= 1) {
            s += __shfl_xor_sync(0xffffffffu, s, o);
            u += __shfl_xor_sync(0xffffffffu, u, o);
        }
        if (lane == 0) { atomicAdd(&g_aS, s); atomicAdd(&g_aU, u); }
    }
}

__global__ void finalize_kernel(float* __restrict__ out) {
    __shared__ float sh[8];
    const int tid  = threadIdx.x;
    const int wid  = tid >> 5;
    const int lane = tid & 31;

    float S = g_rowS[tid];
    float U = g_rowU[tid];
    float ent = logf(S) - U / S;   // per-row entropy
#pragma unroll
    for (int o = 16; o > 0; o >>= 1)
        ent += __shfl_xor_sync(0xffffffffu, ent, o);
    if (lane == 0) sh[wid] = ent;
    __syncthreads();
    if (tid == 0) {
        float tot = 0.f;
#pragma unroll
        for (int w = 0; w < 8; w++) tot += sh[w];
        out[0] = tot * (1.0f / 256.0f);           // L1
        float Sa = g_aS, Ua = g_aU;
        out[1] = Ua / Sa - logf(Sa);              // L2 = -entropy(avg)
    }
}

extern "C" void kernel_launch(void* const* d_in, const int* in_sizes, int n_in,
                              void* d_out, int out_size) {
    const float* x = (const float*)d_in[0];
    float* out = (float*)d_out;
    init_kernel<<<1, 256>>>();
    main_pass<<<NBLK, THREADS>>>(x);
    avg_pass<<<256, 256>>>();
    finalize_kernel<<<1, 256>>>(out);
}

// round 5
// speedup vs baseline: 1.0698x; 1.0143x over previous
#include <cuda_runtime.h>

// LocalityEntropyLoss: feat_map [T=256, F=401408] f32
// L1 = mean over rows of entropy(softmax(row))
// L2 = -entropy(softmax(mean over rows))
// Inputs ~N(0,1): no max-subtraction needed (e^x <= ~100, S ~ 6.6e5, fp32-safe).
// entropy(row) = ln S - U/S,  S = sum e^x, U = sum x e^x.
//
// Single fused main pass:
//  - per-row (S,U) partials  -> smem fold -> global atomics
//  - column sums complete within the block (block owns cols across ALL rows)
//    -> exp(avg) contribution to (Sa,Ua) computed in-block, no colsum array
//  - last block to finish computes both outputs (atomic-counter pattern)

#define T_ROWS 256
#define F_COLS 401408
#define THREADS 128
#define VEC 4
#define CPB (THREADS * VEC)          // 512 columns per block
#define NBLK (F_COLS / CPB)          // 784 blocks
#define NWARP (THREADS / 32)         // 4
#define UNROLL 8

__device__ float g_rowS[T_ROWS];
__device__ float g_rowU[T_ROWS];
__device__ float g_aS;
__device__ float g_aU;
__device__ unsigned int g_done;

__global__ void init_kernel() {
    int t = threadIdx.x;
    if (t < T_ROWS) { g_rowS[t] = 0.0f; g_rowU[t] = 0.0f; }
    if (t == 0) { g_aS = 0.0f; g_aU = 0.0f; g_done = 0u; }
}

__global__ __launch_bounds__(THREADS) void main_pass(const float* __restrict__ x,
                                                     float* __restrict__ out) {
    // 3-step butterfly leaves lanes 0..3 holding disjoint partials of the warp:
    // store 4 partials per (warp, row); fold once at end of block.
    __shared__ float shS[NWARP][T_ROWS][4];   // 16 KB
    __shared__ float shU[NWARP][T_ROWS][4];   // 16 KB
    __shared__ float shA[2 * NWARP];
    __shared__ bool  isLast;

    const int tid  = threadIdx.x;
    const int wid  = tid >> 5;
    const int lane = tid & 31;
    const int colBase = blockIdx.x * CPB + tid * VEC;
    const float4* p = (const float4*)(x + colBase);
    const int stride4 = F_COLS / 4;

    float c0 = 0.f, c1 = 0.f, c2 = 0.f, c3 = 0.f;

#define PROC_ROW(v, rr)                                                         \
    do {                                                                        \
        c0 += (v).x; c1 += (v).y; c2 += (v).z; c3 += (v).w;                     \
        float e0 = __expf((v).x), e1 = __expf((v).y);                           \
        float e2 = __expf((v).z), e3 = __expf((v).w);                           \
        float s = (e0 + e1) + (e2 + e3);                                        \
        float u = fmaf((v).x, e0, fmaf((v).y, e1, fmaf((v).z, e2, (v).w * e3)));\
        s += __shfl_xor_sync(0xffffffffu, s, 16);                               \
        u += __shfl_xor_sync(0xffffffffu, u, 16);                               \
        s += __shfl_xor_sync(0xffffffffu, s, 8);                                \
        u += __shfl_xor_sync(0xffffffffu, u, 8);                                \
        s += __shfl_xor_sync(0xffffffffu, s, 4);                                \
        u += __shfl_xor_sync(0xffffffffu, u, 4);                                \
        if (lane < 4) { shS[wid][rr][lane] = s; shU[wid][rr][lane] = u; }       \
    } while (0)

    for (int r = 0; r < T_ROWS; r += UNROLL) {
        float4 v[UNROLL];
#pragma unroll
        for (int k = 0; k < UNROLL; k++)
            v[k] = __ldcs(&p[(r + k) * stride4]);   // 8 independent loads in flight
#pragma unroll
        for (int k = 0; k < UNROLL; k++)
            PROC_ROW(v[k], r + k);
    }
#undef PROC_ROW

    // ---- avg-vector contribution: c0..c3 are the FINAL column sums ----
    {
        const float inv = 1.0f / 256.0f;
        float a0 = c0 * inv, a1 = c1 * inv, a2 = c2 * inv, a3 = c3 * inv;
        float e0 = __expf(a0), e1 = __expf(a1), e2 = __expf(a2), e3 = __expf(a3);
        float s = (e0 + e1) + (e2 + e3);
        float u = fmaf(a0, e0, fmaf(a1, e1, fmaf(a2, e2, a3 * e3)));
#pragma unroll
        for (int o = 16; o > 0; o >>= 1) {
            s += __shfl_xor_sync(0xffffffffu, s, o);
            u += __shfl_xor_sync(0xffffffffu, u, o);
        }
        if (lane == 0) { shA[wid] = s; shA[NWARP + wid] = u; }
    }

    __syncthreads();

    // Fold the 4x4 warp partials per row; 2 global atomics per row per block.
    for (int rr = tid; rr < T_ROWS; rr += THREADS) {
        float s = 0.f, u = 0.f;
#pragma unroll
        for (int w = 0; w < NWARP; w++) {
            float4 a = *(const float4*)shS[w][rr];
            float4 b = *(const float4*)shU[w][rr];
            s += (a.x + a.y) + (a.z + a.w);
            u += (b.x + b.y) + (b.z + b.w);
        }
        atomicAdd(&g_rowS[rr], s);
        atomicAdd(&g_rowU[rr], u);
    }
    if (tid == 0) {
        float s = 0.f, u = 0.f;
#pragma unroll
        for (int w = 0; w < NWARP; w++) { s += shA[w]; u += shA[NWARP + w]; }
        atomicAdd(&g_aS, s);
        atomicAdd(&g_aU, u);
    }

    // ---- last block finalizes ----
    __threadfence();
    __syncthreads();
    if (tid == 0)
        isLast = (atomicAdd(&g_done, 1u) == (unsigned)(NBLK - 1));
    __syncthreads();

    if (isLast) {
        // each thread handles 2 rows
        float ent = 0.f;
#pragma unroll
        for (int k = 0; k < 2; k++) {
            int rr = tid + k * THREADS;
            float S = g_rowS[rr];
            float U = g_rowU[rr];
            ent += __logf(S) - U / S;
        }
#pragma unroll
        for (int o = 16; o > 0; o >>= 1)
            ent += __shfl_xor_sync(0xffffffffu, ent, o);
        if (lane == 0) shA[wid] = ent;
        __syncthreads();
        if (tid == 0) {
            float tot = 0.f;
#pragma unroll
            for (int w = 0; w < NWARP; w++) tot += shA[w];
            out[0] = tot * (1.0f / 256.0f);            // L1
            float Sa = g_aS, Ua = g_aU;
            out[1] = Ua / Sa - __logf(Sa);             // L2 = -entropy(avg)
        }
    }
}

extern "C" void kernel_launch(void* const* d_in, const int* in_sizes, int n_in,
                              void* d_out, int out_size) {
    const float* x = (const float*)d_in[0];
    float* out = (float*)d_out;
    init_kernel<<<1, 256>>>();
    main_pass<<<NBLK, THREADS>>>(x, out);
}

// round 8
// speedup vs baseline: 1.1428x; 1.0682x over previous
#include <cuda_runtime.h>

// LocalityEntropyLoss: feat_map [T=256, F=401408] f32
// L1 = mean over rows of entropy(softmax(row)); L2 = -entropy(softmax(mean over rows))
// Inputs ~N(0,1): no max-subtraction needed. entropy = ln S - U/S, S=sum e^x, U=sum x e^x.
//
// Single fused pass. Block = 256 threads, owns 512 contiguous columns across ALL rows.
// 4-row joint warp reduction: 3 SHFL per row total (S and U), full per-warp row sums.
// Column sums complete in-block -> avg-entropy contribution computed locally.
// Last block (atomic ticket) writes both outputs.

#define T_ROWS 256
#define F_COLS 401408
#define THREADS 256
#define VEC 2
#define CPB (THREADS * VEC)          // 512 columns per block
#define NBLK (F_COLS / CPB)          // 784 blocks
#define NWARP (THREADS / 32)         // 8
#define UNROLL 8

__device__ float g_rowS[T_ROWS];
__device__ float g_rowU[T_ROWS];
__device__ float g_aS;
__device__ float g_aU;
__device__ unsigned int g_done;

__global__ void init_kernel() {
    int t = threadIdx.x;
    if (t < T_ROWS) { g_rowS[t] = 0.0f; g_rowU[t] = 0.0f; }
    if (t == 0) { g_aS = 0.0f; g_aU = 0.0f; g_done = 0u; }
}

__global__ __launch_bounds__(THREADS, 5) void main_pass(const float* __restrict__ x,
                                                        float* __restrict__ out) {
    __shared__ float shS[NWARP][T_ROWS];   // 8 KB, full per-warp row sums
    __shared__ float shU[NWARP][T_ROWS];   // 8 KB
    __shared__ float shA[2 * NWARP];
    __shared__ bool  isLast;

    const int tid  = threadIdx.x;
    const int wid  = tid >> 5;
    const int lane = tid & 31;
    const int colBase = blockIdx.x * CPB + tid * VEC;
    const float2* p = (const float2*)(x + colBase);
    const int stride2 = F_COLS / 2;

    const unsigned selH = lane & 16;
    const unsigned selQ = lane & 8;
    const int qi = lane >> 3;
    const int row_off = ((qi & 1) << 1) | (qi >> 1);   // quarter -> row {0,2,1,3}
    const bool qrep = ((lane & 7) == 0);

    float c0 = 0.f, c1 = 0.f;

    // per-row (s,u) from this thread's 2 elements
#define ROW_SU(v, sdst, udst)                                   \
    float sdst, udst;                                           \
    {                                                           \
        c0 += (v).x; c1 += (v).y;                               \
        float e0 = __expf((v).x), e1 = __expf((v).y);           \
        sdst = e0 + e1;                                         \
        udst = fmaf((v).x, e0, (v).y * e1);                     \
    }

    // fold 4 rows jointly: 12 SHFL total for (s,u) of 4 rows
#define FOLD4(s0, s1, s2, s3, u0, u1, u2, u3, rbase)                          \
    do {                                                                      \
        float sA = selH ? (s1) : (s0), tA = selH ? (s0) : (s1);               \
        sA += __shfl_xor_sync(0xffffffffu, tA, 16);                           \
        float uA = selH ? (u1) : (u0), tuA = selH ? (u0) : (u1);              \
        uA += __shfl_xor_sync(0xffffffffu, tuA, 16);                          \
        float sB = selH ? (s3) : (s2), tB = selH ? (s2) : (s3);               \
        sB += __shfl_xor_sync(0xffffffffu, tB, 16);                           \
        float uB = selH ? (u3) : (u2), tuB = selH ? (u2) : (u3);              \
        uB += __shfl_xor_sync(0xffffffffu, tuB, 16);                          \
        float sC = selQ ? sB : sA, tC = selQ ? sA : sB;                       \
        sC += __shfl_xor_sync(0xffffffffu, tC, 8);                            \
        float uC = selQ ? uB : uA, tuC = selQ ? uA : uB;                      \
        uC += __shfl_xor_sync(0xffffffffu, tuC, 8);                           \
        sC += __shfl_xor_sync(0xffffffffu, sC, 4);                            \
        uC += __shfl_xor_sync(0xffffffffu, uC, 4);                            \
        sC += __shfl_xor_sync(0xffffffffu, sC, 2);                            \
        uC += __shfl_xor_sync(0xffffffffu, uC, 2);                            \
        sC += __shfl_xor_sync(0xffffffffu, sC, 1);                            \
        uC += __shfl_xor_sync(0xffffffffu, uC, 1);                            \
        if (qrep) { shS[wid][(rbase) + row_off] = sC;                         \
                    shU[wid][(rbase) + row_off] = uC; }                       \
    } while (0)

    for (int r = 0; r < T_ROWS; r += UNROLL) {
        float2 v[UNROLL];
#pragma unroll
        for (int k = 0; k < UNROLL; k++)
            v[k] = __ldcs(&p[(r + k) * stride2]);   // 8 independent loads in flight
        {
            ROW_SU(v[0], s0, u0); ROW_SU(v[1], s1, u1);
            ROW_SU(v[2], s2, u2); ROW_SU(v[3], s3, u3);
            FOLD4(s0, s1, s2, s3, u0, u1, u2, u3, r);
        }
        {
            ROW_SU(v[4], s0, u0); ROW_SU(v[5], s1, u1);
            ROW_SU(v[6], s2, u2); ROW_SU(v[7], s3, u3);
            FOLD4(s0, s1, s2, s3, u0, u1, u2, u3, r + 4);
        }
    }
#undef ROW_SU
#undef FOLD4

    // ---- avg-vector contribution: c0,c1 are the FINAL column sums ----
    {
        const float inv = 1.0f / 256.0f;
        float a0 = c0 * inv, a1 = c1 * inv;
        float e0 = __expf(a0), e1 = __expf(a1);
        float s = e0 + e1;
        float u = fmaf(a0, e0, a1 * e1);
#pragma unroll
        for (int o = 16; o > 0; o >>= 1) {
            s += __shfl_xor_sync(0xffffffffu, s, o);
            u += __shfl_xor_sync(0xffffffffu, u, o);
        }
        if (lane == 0) { shA[wid] = s; shA[NWARP + wid] = u; }
    }

    __syncthreads();

    // Fold the 8 warp row-sums; 2 global atomics per row per block. tid == row.
    {
        float s = 0.f, u = 0.f;
#pragma unroll
        for (int w = 0; w < NWARP; w++) { s += shS[w][tid]; u += shU[w][tid]; }
        atomicAdd(&g_rowS[tid], s);
        atomicAdd(&g_rowU[tid], u);
    }
    if (tid == 0) {
        float s = 0.f, u = 0.f;
#pragma unroll
        for (int w = 0; w < NWARP; w++) { s += shA[w]; u += shA[NWARP + w]; }
        atomicAdd(&g_aS, s);
        atomicAdd(&g_aU, u);
    }

    // ---- last block finalizes ----
    __threadfence();
    __syncthreads();
    if (tid == 0)
        isLast = (atomicAdd(&g_done, 1u) == (unsigned)(NBLK - 1));
    __syncthreads();

    if (isLast) {
        float S = g_rowS[tid];
        float U = g_rowU[tid];
        float ent = __logf(S) - U / S;
#pragma unroll
        for (int o = 16; o > 0; o >>= 1)
            ent += __shfl_xor_sync(0xffffffffu, ent, o);
        if (lane == 0) shA[wid] = ent;
        __syncthreads();
        if (tid == 0) {
            float tot = 0.f;
#pragma unroll
            for (int w = 0; w < NWARP; w++) tot += shA[w];
            out[0] = tot * (1.0f / 256.0f);            // L1
            float Sa = g_aS, Ua = g_aU;
            out[1] = Ua / Sa - __logf(Sa);             // L2 = -entropy(avg)
        }
    }
}

extern "C" void kernel_launch(void* const* d_in, const int* in_sizes, int n_in,
                              void* d_out, int out_size) {
    const float* x = (const float*)d_in[0];
    float* out = (float*)d_out;
    init_kernel<<<1, 256>>>();
    main_pass<<<NBLK, THREADS>>>(x, out);
}

// round 10
// speedup vs baseline: 1.4816x; 1.2965x over previous
#include <cuda_runtime.h>

// LocalityEntropyLoss: feat_map [T=256, F=401408] f32
// L1 = mean over rows of entropy(softmax(row)); L2 = -entropy(softmax(mean over rows))
// Inputs ~N(0,1): no max-subtraction needed. entropy = ln S - U/S, S=sum e^x, U=sum x e^x.
//
// Single fused pass. Block = 256 threads x float4 -> owns 1024 contiguous columns
// across ALL rows (392 blocks, all resident). 4-row joint warp reduction:
// 3 SHFL per row for both (S,U); full per-warp row sums, 16KB smem.
// Column sums complete in-block -> avg-entropy contribution computed locally.
// Last block (atomic ticket) writes both outputs.

#define T_ROWS 256
#define F_COLS 401408
#define THREADS 256
#define VEC 4
#define CPB (THREADS * VEC)          // 1024 columns per block
#define NBLK (F_COLS / CPB)          // 392 blocks
#define NWARP (THREADS / 32)         // 8
#define UNROLL 8

__device__ float g_rowS[T_ROWS];
__device__ float g_rowU[T_ROWS];
__device__ float g_aS;
__device__ float g_aU;
__device__ unsigned int g_done;

__global__ void init_kernel() {
    int t = threadIdx.x;
    if (t < T_ROWS) { g_rowS[t] = 0.0f; g_rowU[t] = 0.0f; }
    if (t == 0) { g_aS = 0.0f; g_aU = 0.0f; g_done = 0u; }
}

__global__ __launch_bounds__(THREADS, 3) void main_pass(const float* __restrict__ x,
                                                        float* __restrict__ out) {
    __shared__ float shS[NWARP][T_ROWS];   // 8 KB, full per-warp row sums
    __shared__ float shU[NWARP][T_ROWS];   // 8 KB
    __shared__ float shA[2 * NWARP];
    __shared__ bool  isLast;

    const int tid  = threadIdx.x;
    const int wid  = tid >> 5;
    const int lane = tid & 31;
    const int colBase = blockIdx.x * CPB + tid * VEC;
    const float4* p = (const float4*)(x + colBase);
    const int stride4 = F_COLS / 4;

    const unsigned selH = lane & 16;
    const unsigned selQ = lane & 8;
    const int qi = lane >> 3;
    const int row_off = ((qi & 1) << 1) | (qi >> 1);   // quarter -> row {0,2,1,3}
    const bool qrep = ((lane & 7) == 0);

    float c0 = 0.f, c1 = 0.f, c2 = 0.f, c3 = 0.f;

    // per-row (s,u) from this thread's 4 elements
#define ROW_SU(v, sdst, udst)                                                   \
    float sdst, udst;                                                           \
    {                                                                           \
        c0 += (v).x; c1 += (v).y; c2 += (v).z; c3 += (v).w;                     \
        float e0 = __expf((v).x), e1 = __expf((v).y);                           \
        float e2 = __expf((v).z), e3 = __expf((v).w);                           \
        sdst = (e0 + e1) + (e2 + e3);                                           \
        udst = fmaf((v).x, e0, fmaf((v).y, e1, fmaf((v).z, e2, (v).w * e3)));   \
    }

    // fold 4 rows jointly: 12 SHFL total for (s,u) of 4 rows
#define FOLD4(s0, s1, s2, s3, u0, u1, u2, u3, rbase)                          \
    do {                                                                      \
        float sA = selH ? (s1) : (s0), tA = selH ? (s0) : (s1);               \
        sA += __shfl_xor_sync(0xffffffffu, tA, 16);                           \
        float uA = selH ? (u1) : (u0), tuA = selH ? (u0) : (u1);              \
        uA += __shfl_xor_sync(0xffffffffu, tuA, 16);                          \
        float sB = selH ? (s3) : (s2), tB = selH ? (s2) : (s3);               \
        sB += __shfl_xor_sync(0xffffffffu, tB, 16);                           \
        float uB = selH ? (u3) : (u2), tuB = selH ? (u2) : (u3);              \
        uB += __shfl_xor_sync(0xffffffffu, tuB, 16);                          \
        float sC = selQ ? sB : sA, tC = selQ ? sA : sB;                       \
        sC += __shfl_xor_sync(0xffffffffu, tC, 8);                            \
        float uC = selQ ? uB : uA, tuC = selQ ? uA : uB;                      \
        uC += __shfl_xor_sync(0xffffffffu, tuC, 8);                           \
        sC += __shfl_xor_sync(0xffffffffu, sC, 4);                            \
        uC += __shfl_xor_sync(0xffffffffu, uC, 4);                            \
        sC += __shfl_xor_sync(0xffffffffu, sC, 2);                            \
        uC += __shfl_xor_sync(0xffffffffu, uC, 2);                            \
        sC += __shfl_xor_sync(0xffffffffu, sC, 1);                            \
        uC += __shfl_xor_sync(0xffffffffu, uC, 1);                            \
        if (qrep) { shS[wid][(rbase) + row_off] = sC;                         \
                    shU[wid][(rbase) + row_off] = uC; }                       \
    } while (0)

    for (int r = 0; r < T_ROWS; r += UNROLL) {
        float4 v[UNROLL];
#pragma unroll
        for (int k = 0; k < UNROLL; k++)
            v[k] = __ldcs(&p[(r + k) * stride4]);   // 8 independent LDG.128 in flight
        {
            ROW_SU(v[0], s0, u0); ROW_SU(v[1], s1, u1);
            ROW_SU(v[2], s2, u2); ROW_SU(v[3], s3, u3);
            FOLD4(s0, s1, s2, s3, u0, u1, u2, u3, r);
        }
        {
            ROW_SU(v[4], s0, u0); ROW_SU(v[5], s1, u1);
            ROW_SU(v[6], s2, u2); ROW_SU(v[7], s3, u3);
            FOLD4(s0, s1, s2, s3, u0, u1, u2, u3, r + 4);
        }
    }
#undef ROW_SU
#undef FOLD4

    // ---- avg-vector contribution: c0..c3 are the FINAL column sums ----
    {
        const float inv = 1.0f / 256.0f;
        float a0 = c0 * inv, a1 = c1 * inv, a2 = c2 * inv, a3 = c3 * inv;
        float e0 = __expf(a0), e1 = __expf(a1), e2 = __expf(a2), e3 = __expf(a3);
        float s = (e0 + e1) + (e2 + e3);
        float u = fmaf(a0, e0, fmaf(a1, e1, fmaf(a2, e2, a3 * e3)));
#pragma unroll
        for (int o = 16; o > 0; o >>= 1) {
            s += __shfl_xor_sync(0xffffffffu, s, o);
            u += __shfl_xor_sync(0xffffffffu, u, o);
        }
        if (lane == 0) { shA[wid] = s; shA[NWARP + wid] = u; }
    }

    __syncthreads();

    // Fold the 8 warp row-sums; 2 global atomics per row per block. tid == row.
    {
        float s = 0.f, u = 0.f;
#pragma unroll
        for (int w = 0; w < NWARP; w++) { s += shS[w][tid]; u += shU[w][tid]; }
        atomicAdd(&g_rowS[tid], s);
        atomicAdd(&g_rowU[tid], u);
    }
    if (tid == 0) {
        float s = 0.f, u = 0.f;
#pragma unroll
        for (int w = 0; w < NWARP; w++) { s += shA[w]; u += shA[NWARP + w]; }
        atomicAdd(&g_aS, s);
        atomicAdd(&g_aU, u);
    }

    // ---- last block finalizes ----
    __threadfence();
    __syncthreads();
    if (tid == 0)
        isLast = (atomicAdd(&g_done, 1u) == (unsigned)(NBLK - 1));
    __syncthreads();

    if (isLast) {
        float S = g_rowS[tid];
        float U = g_rowU[tid];
        float ent = __logf(S) - U / S;
#pragma unroll
        for (int o = 16; o > 0; o >>= 1)
            ent += __shfl_xor_sync(0xffffffffu, ent, o);
        if (lane == 0) shA[wid] = ent;
        __syncthreads();
        if (tid == 0) {
            float tot = 0.f;
#pragma unroll
            for (int w = 0; w < NWARP; w++) tot += shA[w];
            out[0] = tot * (1.0f / 256.0f);            // L1
            float Sa = g_aS, Ua = g_aU;
            out[1] = Ua / Sa - __logf(Sa);             // L2 = -entropy(avg)
        }
    }
}

extern "C" void kernel_launch(void* const* d_in, const int* in_sizes, int n_in,
                              void* d_out, int out_size) {
    const float* x = (const float*)d_in[0];
    float* out = (float*)d_out;
    init_kernel<<<1, 256>>>();
    main_pass<<<NBLK, THREADS>>>(x, out);
}